// round 3
// baseline (speedup 1.0000x reference)
#include <cuda_runtime.h>
#include <cuda_fp16.h>

#define HID 128
#define MAXN 50176
#define MAXE 1605632

__device__ __align__(16) __half g_hh [(size_t)MAXN * HID];  // layer-0 features (fp16)
__device__ __align__(16) __half g_hbh[(size_t)MAXN * HID];  // layer-1 features (fp16)
__device__ float g_si[MAXN];
__device__ float g_sj[MAXN];
__device__ int   g_deg[MAXN];
__device__ int   g_start[MAXN];
__device__ int   g_cursor[MAXN];
__device__ int   g_sorted[MAXE];   // src ids grouped by dst (CSR adjacency)
__device__ int   g_is64;

// ---------------------------------------------------------------------------
// Edge-index dtype detection: int64 little-endian values < 50000 have all-zero
// odd 32-bit words; int32 edge data does not.
// ---------------------------------------------------------------------------
__global__ void detect64_kernel(const int* __restrict__ p, int twoE) {
    __shared__ int any_nonzero;
    if (threadIdx.x == 0) any_nonzero = 0;
    __syncthreads();
    int local = 0;
    int half = twoE >> 1;
    for (int i = threadIdx.x; i < 4096; i += blockDim.x) {
        long long q = (long long)i * half / 4096;
        long long idx = 2 * q + 1;
        if (idx < twoE) local |= p[idx];
    }
    if (local) atomicOr(&any_nonzero, 1);
    __syncthreads();
    if (threadIdx.x == 0) g_is64 = (any_nonzero == 0) ? 1 : 0;
}

// ---------------------------------------------------------------------------
// CSR build: histogram -> exclusive scan -> cursor scatter (decode in place)
// ---------------------------------------------------------------------------
__global__ void zero_deg_kernel(int n) {
    int i = blockIdx.x * blockDim.x + threadIdx.x;
    if (i < n) g_deg[i] = 0;
}

__global__ void hist_kernel(const int* __restrict__ p, int E) {
    int e = blockIdx.x * blockDim.x + threadIdx.x;
    if (e >= E) return;
    int d = g_is64 ? p[2 * (E + e)] : p[E + e];
    atomicAdd(&g_deg[d], 1);
}

// Single-block exclusive scan over n bins (1024 threads, chunked).
__global__ void scan_kernel(int n) {
    __shared__ int warp_tot[32];
    __shared__ int carry_s;
    int tid = threadIdx.x;
    int lane = tid & 31;
    int wid = tid >> 5;
    if (tid == 0) carry_s = 0;
    __syncthreads();
    for (int base = 0; base < n; base += 1024) {
        int i = base + tid;
        int v = (i < n) ? g_deg[i] : 0;
        int x = v;
#pragma unroll
        for (int o = 1; o < 32; o <<= 1) {
            int y = __shfl_up_sync(0xFFFFFFFFu, x, o);
            if (lane >= o) x += y;
        }
        if (lane == 31) warp_tot[wid] = x;
        __syncthreads();
        if (wid == 0) {
            int t = warp_tot[lane];
#pragma unroll
            for (int o = 1; o < 32; o <<= 1) {
                int y = __shfl_up_sync(0xFFFFFFFFu, t, o);
                if (lane >= o) t += y;
            }
            warp_tot[lane] = t;
        }
        __syncthreads();
        int warp_off = wid ? warp_tot[wid - 1] : 0;
        int incl = x + warp_off;
        int c = carry_s;
        if (i < n) g_start[i] = c + incl - v;
        __syncthreads();
        if (tid == 1023) carry_s = c + incl;
        __syncthreads();
    }
}

__global__ void init_cursor_kernel(int n) {
    int i = blockIdx.x * blockDim.x + threadIdx.x;
    if (i < n) g_cursor[i] = g_start[i];
}

__global__ void scatter_kernel(const int* __restrict__ p, int E) {
    int e = blockIdx.x * blockDim.x + threadIdx.x;
    if (e >= E) return;
    int s, d;
    if (g_is64) { s = p[2 * e]; d = p[2 * (E + e)]; }
    else        { s = p[e];     d = p[E + e]; }
    int pos = atomicAdd(&g_cursor[d], 1);
    g_sorted[pos] = s;
}

// ---------------------------------------------------------------------------
// Encoder GEMM: g_hh = fp16(relu(x[M,256] @ W[256,128] + b[128]))
// ---------------------------------------------------------------------------
__global__ void __launch_bounds__(256) gemm_relu_kernel(
        const float* __restrict__ A, const float* __restrict__ W,
        const float* __restrict__ bias, int M) {
    const int K = 256;
    __shared__ float As[16][132];
    __shared__ float Bs[16][128];

    int tid = threadIdx.x;
    int tx = tid % 16;
    int ty = tid / 16;
    int block_m = blockIdx.x * 128;

    float acc[8][8];
#pragma unroll
    for (int i = 0; i < 8; i++)
#pragma unroll
        for (int j = 0; j < 8; j++) acc[i][j] = 0.f;

    for (int k0 = 0; k0 < K; k0 += 16) {
        for (int t = tid; t < 512; t += 256) {
            int r  = t >> 2;
            int c4 = t & 3;
            int row = block_m + r;
            float4 v = make_float4(0.f, 0.f, 0.f, 0.f);
            if (row < M)
                v = *(const float4*)(A + (size_t)row * K + k0 + c4 * 4);
            As[c4 * 4 + 0][r] = v.x;
            As[c4 * 4 + 1][r] = v.y;
            As[c4 * 4 + 2][r] = v.z;
            As[c4 * 4 + 3][r] = v.w;
        }
        for (int t = tid; t < 512; t += 256) {
            int r  = t >> 5;
            int c4 = t & 31;
            float4 v = *(const float4*)(W + (size_t)(k0 + r) * 128 + c4 * 4);
            *(float4*)&Bs[r][c4 * 4] = v;
        }
        __syncthreads();
#pragma unroll
        for (int k = 0; k < 16; k++) {
            float a[8], b[8];
#pragma unroll
            for (int i = 0; i < 8; i++) a[i] = As[k][ty * 8 + i];
#pragma unroll
            for (int j = 0; j < 8; j++) b[j] = Bs[k][tx * 8 + j];
#pragma unroll
            for (int i = 0; i < 8; i++)
#pragma unroll
                for (int j = 0; j < 8; j++) acc[i][j] += a[i] * b[j];
        }
        __syncthreads();
    }

#pragma unroll
    for (int i = 0; i < 8; i++) {
        int row = block_m + ty * 8 + i;
        if (row >= M) continue;
        __half tmp[8];
#pragma unroll
        for (int j = 0; j < 8; j++) {
            int col = tx * 8 + j;
            float v = acc[i][j] + bias[col];
            tmp[j] = __float2half_rn(v > 0.f ? v : 0.f);
        }
        *(uint4*)(g_hh + (size_t)row * HID + tx * 8) = *(uint4*)tmp;
    }
}

// ---------------------------------------------------------------------------
// Per-node attention scalars from fp16 features: si=h.w[:128], sj=h.w[128:]
// ---------------------------------------------------------------------------
__global__ void dots_kernel(const float* __restrict__ w, int n, int useB) {
    int warp = (blockIdx.x * blockDim.x + threadIdx.x) >> 5;
    int lane = threadIdx.x & 31;
    if (warp >= n) return;
    const __half* hp = (useB ? g_hbh : g_hh) + (size_t)warp * HID;
    uint2 raw = *((const uint2*)hp + lane);
    __half2 h01 = *(__half2*)&raw.x;
    __half2 h23 = *(__half2*)&raw.y;
    float2 f01 = __half22float2(h01);
    float2 f23 = __half22float2(h23);
    float4 wi = ((const float4*)w)[lane];
    float4 wj = ((const float4*)w)[32 + lane];
    float si = f01.x * wi.x + f01.y * wi.y + f23.x * wi.z + f23.y * wi.w;
    float sj = f01.x * wj.x + f01.y * wj.y + f23.x * wj.z + f23.y * wj.w;
#pragma unroll
    for (int o = 16; o; o >>= 1) {
        si += __shfl_xor_sync(0xFFFFFFFFu, si, o);
        sj += __shfl_xor_sync(0xFFFFFFFFu, sj, o);
    }
    if (lane == 0) { g_si[warp] = si; g_sj[warp] = sj; }
}

// ---------------------------------------------------------------------------
// Layer 1: warp per node; acc = sum_e sigmoid(si[d]+sj[s]+b)*h[s];
// g_hbh[d] = fp16(relu(acc / max(deg,1)))
// ---------------------------------------------------------------------------
__global__ void agg1_kernel(const float* __restrict__ bptr, int n) {
    int d = (blockIdx.x * blockDim.x + threadIdx.x) >> 5;
    int lane = threadIdx.x & 31;
    if (d >= n) return;
    int k0 = g_start[d];
    int deg = g_deg[d];
    float si = g_si[d];
    float b = bptr[0];
    float ax = 0.f, ay = 0.f, az = 0.f, aw = 0.f;
#pragma unroll 4
    for (int k = k0; k < k0 + deg; k++) {
        int s = g_sorted[k];
        float z = si + g_sj[s] + b;
        float alpha = 1.0f / (1.0f + __expf(-z));
        uint2 raw = *((const uint2*)(g_hh + (size_t)s * HID) + lane);
        float2 f01 = __half22float2(*(__half2*)&raw.x);
        float2 f23 = __half22float2(*(__half2*)&raw.y);
        ax += alpha * f01.x; ay += alpha * f01.y;
        az += alpha * f23.x; aw += alpha * f23.y;
    }
    float inv = 1.0f / (float)(deg < 1 ? 1 : deg);
    ax *= inv; ay *= inv; az *= inv; aw *= inv;
    ax = ax > 0.f ? ax : 0.f;
    ay = ay > 0.f ? ay : 0.f;
    az = az > 0.f ? az : 0.f;
    aw = aw > 0.f ? aw : 0.f;
    __half tmp[4];
    tmp[0] = __float2half_rn(ax); tmp[1] = __float2half_rn(ay);
    tmp[2] = __float2half_rn(az); tmp[3] = __float2half_rn(aw);
    *((uint2*)(g_hbh + (size_t)d * HID) + lane) = *(uint2*)tmp;
}

// ---------------------------------------------------------------------------
// Layer 2 + classifier fused: warp per node; v = acc/max(deg,1);
// out[d] = v @ cls_w + cls_b
// ---------------------------------------------------------------------------
__global__ void agg2_cls_kernel(const float* __restrict__ bptr,
                                const float* __restrict__ clsw,
                                const float* __restrict__ clsb,
                                float* __restrict__ out, int n) {
    int d = (blockIdx.x * blockDim.x + threadIdx.x) >> 5;
    int lane = threadIdx.x & 31;
    if (d >= n) return;
    int k0 = g_start[d];
    int deg = g_deg[d];
    float si = g_si[d];
    float b = bptr[0];
    float ax = 0.f, ay = 0.f, az = 0.f, aw = 0.f;
#pragma unroll 4
    for (int k = k0; k < k0 + deg; k++) {
        int s = g_sorted[k];
        float z = si + g_sj[s] + b;
        float alpha = 1.0f / (1.0f + __expf(-z));
        uint2 raw = *((const uint2*)(g_hbh + (size_t)s * HID) + lane);
        float2 f01 = __half22float2(*(__half2*)&raw.x);
        float2 f23 = __half22float2(*(__half2*)&raw.y);
        ax += alpha * f01.x; ay += alpha * f01.y;
        az += alpha * f23.x; aw += alpha * f23.y;
    }
    float inv = 1.0f / (float)(deg < 1 ? 1 : deg);
    ax *= inv; ay *= inv; az *= inv; aw *= inv;
    int j = lane * 4;
    float o0 = ax * clsw[(j + 0) * 2] + ay * clsw[(j + 1) * 2] +
               az * clsw[(j + 2) * 2] + aw * clsw[(j + 3) * 2];
    float o1 = ax * clsw[(j + 0) * 2 + 1] + ay * clsw[(j + 1) * 2 + 1] +
               az * clsw[(j + 2) * 2 + 1] + aw * clsw[(j + 3) * 2 + 1];
#pragma unroll
    for (int o = 16; o; o >>= 1) {
        o0 += __shfl_xor_sync(0xFFFFFFFFu, o0, o);
        o1 += __shfl_xor_sync(0xFFFFFFFFu, o1, o);
    }
    if (lane == 0) {
        out[(size_t)d * 2 + 0] = o0 + clsb[0];
        out[(size_t)d * 2 + 1] = o1 + clsb[1];
    }
}

// ---------------------------------------------------------------------------
extern "C" void kernel_launch(void* const* d_in, const int* in_sizes, int n_in,
                              void* d_out, int out_size) {
    const float* x      = (const float*)d_in[0];
    const int*   ei     = (const int*)  d_in[1];
    const float* enc_w  = (const float*)d_in[2];
    const float* enc_b  = (const float*)d_in[3];
    const float* att1_w = (const float*)d_in[4];
    const float* att1_b = (const float*)d_in[5];
    const float* att2_w = (const float*)d_in[6];
    const float* att2_b = (const float*)d_in[7];
    const float* cls_w  = (const float*)d_in[8];
    const float* cls_b  = (const float*)d_in[9];
    float* out = (float*)d_out;

    int N = in_sizes[0] / 256;
    int E = in_sizes[1] / 2;

    // Decode dtype; CSR build (grouped by dst), edge decode fused in.
    detect64_kernel<<<1, 1024>>>(ei, 2 * E);
    zero_deg_kernel<<<(N + 255) / 256, 256>>>(N);
    hist_kernel<<<(E + 255) / 256, 256>>>(ei, E);
    scan_kernel<<<1, 1024>>>(N);
    init_cursor_kernel<<<(N + 255) / 256, 256>>>(N);
    scatter_kernel<<<(E + 255) / 256, 256>>>(ei, E);

    // Encoder
    gemm_relu_kernel<<<(N + 127) / 128, 256>>>(x, enc_w, enc_b, N);

    int node_warp_blocks = (N + 7) / 8;  // warp per node, 8 warps/block

    // Layer 1
    dots_kernel<<<node_warp_blocks, 256>>>(att1_w, N, 0);
    agg1_kernel<<<node_warp_blocks, 256>>>(att1_b, N);

    // Layer 2 (+ classifier)
    dots_kernel<<<node_warp_blocks, 256>>>(att2_w, N, 1);
    agg2_cls_kernel<<<node_warp_blocks, 256>>>(att2_b, cls_w, cls_b, out, N);
}

// round 5
// speedup vs baseline: 1.5804x; 1.5804x over previous
#include <cuda_runtime.h>
#include <cuda_fp16.h>
#include <cstdint>

#define HID 128
#define MAXN 50176
#define MAXE 1605632
#define SCAN_BLOCKS 64

__device__ __align__(16) __half g_hh [(size_t)MAXN * HID];  // layer-0 features (fp16)
__device__ __align__(16) __half g_hbh[(size_t)MAXN * HID];  // layer-1 features (fp16)
__device__ float g_si[MAXN];
__device__ float g_sj[MAXN];
__device__ int   g_deg[MAXN];
__device__ int   g_start[MAXN];
__device__ int   g_cursor[MAXN];
__device__ int   g_sorted[MAXE];   // src ids grouped by dst (CSR adjacency)
__device__ int   g_bsum[SCAN_BLOCKS];
__device__ int   g_boff[SCAN_BLOCKS];
__device__ int   g_is64;

// ---------------------------------------------------------------------------
// Edge-index dtype detection: int64 little-endian values < 50000 have all-zero
// odd 32-bit words; int32 edge data does not.
// ---------------------------------------------------------------------------
__global__ void detect64_kernel(const int* __restrict__ p, int twoE) {
    __shared__ int any_nonzero;
    if (threadIdx.x == 0) any_nonzero = 0;
    __syncthreads();
    int local = 0;
    int half = twoE >> 1;
    for (int i = threadIdx.x; i < 4096; i += blockDim.x) {
        long long q = (long long)i * half / 4096;
        long long idx = 2 * q + 1;
        if (idx < twoE) local |= p[idx];
    }
    if (local) atomicOr(&any_nonzero, 1);
    __syncthreads();
    if (threadIdx.x == 0) g_is64 = (any_nonzero == 0) ? 1 : 0;
}

// ---------------------------------------------------------------------------
// CSR build: histogram -> parallel 3-stage scan -> cursor scatter
// ---------------------------------------------------------------------------
__global__ void zero_deg_kernel(int n) {
    int i = blockIdx.x * blockDim.x + threadIdx.x;
    if (i < n) g_deg[i] = 0;
}

__global__ void hist_kernel(const int* __restrict__ p, int E) {
    int e = blockIdx.x * blockDim.x + threadIdx.x;
    if (e >= E) return;
    int d = g_is64 ? p[2 * (E + e)] : p[E + e];
    atomicAdd(&g_deg[d], 1);
}

// Stage 1: per-block (1024-wide) exclusive scan; block total to g_bsum.
__global__ void scan_block_kernel(int n) {
    __shared__ int warp_tot[32];
    int tid = threadIdx.x;
    int lane = tid & 31;
    int wid = tid >> 5;
    int i = blockIdx.x * 1024 + tid;
    int v = (i < n) ? g_deg[i] : 0;
    int x = v;
#pragma unroll
    for (int o = 1; o < 32; o <<= 1) {
        int y = __shfl_up_sync(0xFFFFFFFFu, x, o);
        if (lane >= o) x += y;
    }
    if (lane == 31) warp_tot[wid] = x;
    __syncthreads();
    if (wid == 0) {
        int t = warp_tot[lane];
#pragma unroll
        for (int o = 1; o < 32; o <<= 1) {
            int y = __shfl_up_sync(0xFFFFFFFFu, t, o);
            if (lane >= o) t += y;
        }
        warp_tot[lane] = t;
    }
    __syncthreads();
    int off = wid ? warp_tot[wid - 1] : 0;
    int incl = x + off;
    if (i < n) g_start[i] = incl - v;
    if (tid == 1023) g_bsum[blockIdx.x] = incl;
}

// Stage 2: one warp scans block sums (nb <= 64), 2 elements per lane.
__global__ void scan_bsum_kernel(int nb) {
    int lane = threadIdx.x;
    int v0 = (2 * lane     < nb) ? g_bsum[2 * lane]     : 0;
    int v1 = (2 * lane + 1 < nb) ? g_bsum[2 * lane + 1] : 0;
    int p = v0 + v1;
    int x = p;
#pragma unroll
    for (int o = 1; o < 32; o <<= 1) {
        int y = __shfl_up_sync(0xFFFFFFFFu, x, o);
        if (lane >= o) x += y;
    }
    int excl = x - p;
    if (2 * lane     < nb) g_boff[2 * lane]     = excl;
    if (2 * lane + 1 < nb) g_boff[2 * lane + 1] = excl + v0;
}

// Stage 3: add block offsets; init cursors.
__global__ void add_off_kernel(int n) {
    int i = blockIdx.x * blockDim.x + threadIdx.x;
    if (i < n) {
        int s = g_start[i] + g_boff[i >> 10];
        g_start[i] = s;
        g_cursor[i] = s;
    }
}

__global__ void scatter_kernel(const int* __restrict__ p, int E) {
    int e = blockIdx.x * blockDim.x + threadIdx.x;
    if (e >= E) return;
    int s, d;
    if (g_is64) { s = p[2 * e]; d = p[2 * (E + e)]; }
    else        { s = p[e];     d = p[E + e]; }
    int pos = atomicAdd(&g_cursor[d], 1);
    g_sorted[pos] = s;
}

// ---------------------------------------------------------------------------
// Encoder GEMM via tensor cores (fp16 in, fp32 accum):
// g_hh = fp16(relu(x[M,256] @ W[256,128] + b[128]))
// 128x128 block tile, BK=32, 8 warps (2m x 4n), mma.m16n8k16.
// Padded smem rows (A: 40 halves, B: 136 halves) -> conflict-free ldmatrix.
// ---------------------------------------------------------------------------
__device__ __forceinline__ void ldsm_x4(unsigned* a, uint32_t addr) {
    asm volatile("ldmatrix.sync.aligned.m8n8.x4.shared.b16 {%0,%1,%2,%3}, [%4];"
                 : "=r"(a[0]), "=r"(a[1]), "=r"(a[2]), "=r"(a[3]) : "r"(addr));
}
__device__ __forceinline__ void ldsm_x2_trans(unsigned* b, uint32_t addr) {
    asm volatile("ldmatrix.sync.aligned.m8n8.x2.trans.shared.b16 {%0,%1}, [%2];"
                 : "=r"(b[0]), "=r"(b[1]) : "r"(addr));
}
__device__ __forceinline__ void mma16816(float* c, const unsigned* a, const unsigned* b) {
    asm volatile("mma.sync.aligned.m16n8k16.row.col.f32.f16.f16.f32 "
                 "{%0,%1,%2,%3}, {%4,%5,%6,%7}, {%8,%9}, {%0,%1,%2,%3};"
                 : "+f"(c[0]), "+f"(c[1]), "+f"(c[2]), "+f"(c[3])
                 : "r"(a[0]), "r"(a[1]), "r"(a[2]), "r"(a[3]),
                   "r"(b[0]), "r"(b[1]));
}

__global__ void __launch_bounds__(256) gemm_mma_kernel(
        const float* __restrict__ A, const float* __restrict__ W,
        const float* __restrict__ bias, int M) {
    const int LDA = 40;    // halves per A smem row (80 B)
    const int LDB = 136;   // halves per B smem row (272 B)
    __shared__ __half As[128 * LDA];
    __shared__ __half Bs[32 * LDB];

    int tid = threadIdx.x;
    int warp = tid >> 5;
    int lane = tid & 31;
    int warp_m = warp >> 2;   // 0..1
    int warp_n = warp & 3;    // 0..3
    int bm = blockIdx.x * 128;

    uint32_t sA = (uint32_t)__cvta_generic_to_shared(As);
    uint32_t sB = (uint32_t)__cvta_generic_to_shared(Bs);

    float c[4][4][4];
#pragma unroll
    for (int mt = 0; mt < 4; mt++)
#pragma unroll
        for (int nt = 0; nt < 4; nt++)
#pragma unroll
            for (int r = 0; r < 4; r++) c[mt][nt][r] = 0.f;

    for (int k0 = 0; k0 < 256; k0 += 32) {
        // A tile: 128 rows x 32 cols fp32 -> fp16 (1024 float4 loads)
#pragma unroll
        for (int i = 0; i < 4; i++) {
            int t = tid + i * 256;
            int r = t >> 3;
            int c4 = t & 7;
            int row = bm + r;
            float4 v = make_float4(0.f, 0.f, 0.f, 0.f);
            if (row < M)
                v = *(const float4*)(A + (size_t)row * 256 + k0 + c4 * 4);
            __half2 h01 = __floats2half2_rn(v.x, v.y);
            __half2 h23 = __floats2half2_rn(v.z, v.w);
            uint2 u = make_uint2(*(unsigned*)&h01, *(unsigned*)&h23);
            *(uint2*)(As + r * LDA + c4 * 4) = u;
        }
        // B tile: 32 rows x 128 cols fp32 -> fp16
#pragma unroll
        for (int i = 0; i < 4; i++) {
            int t = tid + i * 256;
            int r = t >> 5;
            int c4 = t & 31;
            float4 v = *(const float4*)(W + (size_t)(k0 + r) * 128 + c4 * 4);
            __half2 h01 = __floats2half2_rn(v.x, v.y);
            __half2 h23 = __floats2half2_rn(v.z, v.w);
            uint2 u = make_uint2(*(unsigned*)&h01, *(unsigned*)&h23);
            *(uint2*)(Bs + r * LDB + c4 * 4) = u;
        }
        __syncthreads();
#pragma unroll
        for (int ks = 0; ks < 2; ks++) {
            int ko = ks * 16;
            unsigned a[4][4], b[4][2];
#pragma unroll
            for (int mt = 0; mt < 4; mt++) {
                uint32_t addr = sA + 2u * (uint32_t)((warp_m * 64 + mt * 16 + (lane & 15)) * LDA
                                           + ko + (lane >> 4) * 8);
                ldsm_x4(a[mt], addr);
            }
#pragma unroll
            for (int nt = 0; nt < 4; nt++) {
                uint32_t addr = sB + 2u * (uint32_t)((ko + (lane & 15)) * LDB
                                           + warp_n * 32 + nt * 8);
                ldsm_x2_trans(b[nt], addr);
            }
#pragma unroll
            for (int mt = 0; mt < 4; mt++)
#pragma unroll
                for (int nt = 0; nt < 4; nt++)
                    mma16816(c[mt][nt], a[mt], b[nt]);
        }
        __syncthreads();
    }

    // Epilogue: bias + relu + fp16 store
#pragma unroll
    for (int nt = 0; nt < 4; nt++) {
        int col = warp_n * 32 + nt * 8 + (lane & 3) * 2;
        float b0 = __ldg(bias + col);
        float b1 = __ldg(bias + col + 1);
#pragma unroll
        for (int mt = 0; mt < 4; mt++) {
            int row = bm + warp_m * 64 + mt * 16 + (lane >> 2);
            if (row < M) {
                float v0 = c[mt][nt][0] + b0;
                float v1 = c[mt][nt][1] + b1;
                __half2 h = __floats2half2_rn(v0 > 0.f ? v0 : 0.f,
                                              v1 > 0.f ? v1 : 0.f);
                *(__half2*)(g_hh + (size_t)row * HID + col) = h;
            }
            if (row + 8 < M) {
                float v0 = c[mt][nt][2] + b0;
                float v1 = c[mt][nt][3] + b1;
                __half2 h = __floats2half2_rn(v0 > 0.f ? v0 : 0.f,
                                              v1 > 0.f ? v1 : 0.f);
                *(__half2*)(g_hh + (size_t)(row + 8) * HID + col) = h;
            }
        }
    }
}

// ---------------------------------------------------------------------------
// Per-node attention scalars from fp16 features: si=h.w[:128], sj=h.w[128:]
// ---------------------------------------------------------------------------
__global__ void dots_kernel(const float* __restrict__ w, int n, int useB) {
    int warp = (blockIdx.x * blockDim.x + threadIdx.x) >> 5;
    int lane = threadIdx.x & 31;
    if (warp >= n) return;
    const __half* hp = (useB ? g_hbh : g_hh) + (size_t)warp * HID;
    uint2 raw = *((const uint2*)hp + lane);
    float2 f01 = __half22float2(*(__half2*)&raw.x);
    float2 f23 = __half22float2(*(__half2*)&raw.y);
    float4 wi = ((const float4*)w)[lane];
    float4 wj = ((const float4*)w)[32 + lane];
    float si = f01.x * wi.x + f01.y * wi.y + f23.x * wi.z + f23.y * wi.w;
    float sj = f01.x * wj.x + f01.y * wj.y + f23.x * wj.z + f23.y * wj.w;
#pragma unroll
    for (int o = 16; o; o >>= 1) {
        si += __shfl_xor_sync(0xFFFFFFFFu, si, o);
        sj += __shfl_xor_sync(0xFFFFFFFFu, sj, o);
    }
    if (lane == 0) { g_si[warp] = si; g_sj[warp] = sj; }
}

// ---------------------------------------------------------------------------
// Layer 1: warp per node; acc = sum_e sigmoid(si[d]+sj[s]+b)*h[s];
// g_hbh[d] = fp16(relu(acc / max(deg,1)))
// ---------------------------------------------------------------------------
__global__ void agg1_kernel(const float* __restrict__ bptr, int n) {
    int d = (blockIdx.x * blockDim.x + threadIdx.x) >> 5;
    int lane = threadIdx.x & 31;
    if (d >= n) return;
    int k0 = g_start[d];
    int deg = g_deg[d];
    float si = g_si[d];
    float b = bptr[0];
    float ax = 0.f, ay = 0.f, az = 0.f, aw = 0.f;
#pragma unroll 4
    for (int k = k0; k < k0 + deg; k++) {
        int s = g_sorted[k];
        float z = si + g_sj[s] + b;
        float alpha = 1.0f / (1.0f + __expf(-z));
        uint2 raw = *((const uint2*)(g_hh + (size_t)s * HID) + lane);
        float2 f01 = __half22float2(*(__half2*)&raw.x);
        float2 f23 = __half22float2(*(__half2*)&raw.y);
        ax += alpha * f01.x; ay += alpha * f01.y;
        az += alpha * f23.x; aw += alpha * f23.y;
    }
    float inv = 1.0f / (float)(deg < 1 ? 1 : deg);
    ax *= inv; ay *= inv; az *= inv; aw *= inv;
    __half2 h01 = __floats2half2_rn(ax > 0.f ? ax : 0.f, ay > 0.f ? ay : 0.f);
    __half2 h23 = __floats2half2_rn(az > 0.f ? az : 0.f, aw > 0.f ? aw : 0.f);
    uint2 u = make_uint2(*(unsigned*)&h01, *(unsigned*)&h23);
    *((uint2*)(g_hbh + (size_t)d * HID) + lane) = u;
}

// ---------------------------------------------------------------------------
// Layer 2 + classifier fused: warp per node; v = acc/max(deg,1);
// out[d] = v @ cls_w + cls_b
// ---------------------------------------------------------------------------
__global__ void agg2_cls_kernel(const float* __restrict__ bptr,
                                const float* __restrict__ clsw,
                                const float* __restrict__ clsb,
                                float* __restrict__ out, int n) {
    int d = (blockIdx.x * blockDim.x + threadIdx.x) >> 5;
    int lane = threadIdx.x & 31;
    if (d >= n) return;
    int k0 = g_start[d];
    int deg = g_deg[d];
    float si = g_si[d];
    float b = bptr[0];
    float ax = 0.f, ay = 0.f, az = 0.f, aw = 0.f;
#pragma unroll 4
    for (int k = k0; k < k0 + deg; k++) {
        int s = g_sorted[k];
        float z = si + g_sj[s] + b;
        float alpha = 1.0f / (1.0f + __expf(-z));
        uint2 raw = *((const uint2*)(g_hbh + (size_t)s * HID) + lane);
        float2 f01 = __half22float2(*(__half2*)&raw.x);
        float2 f23 = __half22float2(*(__half2*)&raw.y);
        ax += alpha * f01.x; ay += alpha * f01.y;
        az += alpha * f23.x; aw += alpha * f23.y;
    }
    float inv = 1.0f / (float)(deg < 1 ? 1 : deg);
    ax *= inv; ay *= inv; az *= inv; aw *= inv;
    int j = lane * 4;
    float o0 = ax * clsw[(j + 0) * 2] + ay * clsw[(j + 1) * 2] +
               az * clsw[(j + 2) * 2] + aw * clsw[(j + 3) * 2];
    float o1 = ax * clsw[(j + 0) * 2 + 1] + ay * clsw[(j + 1) * 2 + 1] +
               az * clsw[(j + 2) * 2 + 1] + aw * clsw[(j + 3) * 2 + 1];
#pragma unroll
    for (int o = 16; o; o >>= 1) {
        o0 += __shfl_xor_sync(0xFFFFFFFFu, o0, o);
        o1 += __shfl_xor_sync(0xFFFFFFFFu, o1, o);
    }
    if (lane == 0) {
        out[(size_t)d * 2 + 0] = o0 + clsb[0];
        out[(size_t)d * 2 + 1] = o1 + clsb[1];
    }
}

// ---------------------------------------------------------------------------
extern "C" void kernel_launch(void* const* d_in, const int* in_sizes, int n_in,
                              void* d_out, int out_size) {
    const float* x      = (const float*)d_in[0];
    const int*   ei     = (const int*)  d_in[1];
    const float* enc_w  = (const float*)d_in[2];
    const float* enc_b  = (const float*)d_in[3];
    const float* att1_w = (const float*)d_in[4];
    const float* att1_b = (const float*)d_in[5];
    const float* att2_w = (const float*)d_in[6];
    const float* att2_b = (const float*)d_in[7];
    const float* cls_w  = (const float*)d_in[8];
    const float* cls_b  = (const float*)d_in[9];
    float* out = (float*)d_out;

    int N = in_sizes[0] / 256;
    int E = in_sizes[1] / 2;
    int nb = (N + 1023) / 1024;

    // Decode dtype; CSR build (grouped by dst), edge decode fused in.
    detect64_kernel<<<1, 1024>>>(ei, 2 * E);
    zero_deg_kernel<<<(N + 255) / 256, 256>>>(N);
    hist_kernel<<<(E + 255) / 256, 256>>>(ei, E);
    scan_block_kernel<<<nb, 1024>>>(N);
    scan_bsum_kernel<<<1, 32>>>(nb);
    add_off_kernel<<<(N + 255) / 256, 256>>>(N);
    scatter_kernel<<<(E + 255) / 256, 256>>>(ei, E);

    // Encoder (tensor cores)
    gemm_mma_kernel<<<(N + 127) / 128, 256>>>(x, enc_w, enc_b, N);

    int node_warp_blocks = (N + 7) / 8;  // warp per node, 8 warps/block

    // Layer 1
    dots_kernel<<<node_warp_blocks, 256>>>(att1_w, N, 0);
    agg1_kernel<<<node_warp_blocks, 256>>>(att1_b, N);

    // Layer 2 (+ classifier)
    dots_kernel<<<node_warp_blocks, 256>>>(att2_w, N, 1);
    agg2_cls_kernel<<<node_warp_blocks, 256>>>(att2_b, cls_w, cls_b, out, N);
}

// round 6
// speedup vs baseline: 1.7276x; 1.0931x over previous
#include <cuda_runtime.h>
#include <cuda_fp16.h>
#include <cstdint>

#define HID 128
#define MAXN 50176
#define MAXE 1605632
#define SCAN_BLOCKS 64

__device__ __align__(16) __half g_hh [(size_t)MAXN * HID];  // layer-0 features (fp16)
__device__ __align__(16) __half g_hbh[(size_t)MAXN * HID];  // layer-1 features (fp16)
__device__ float g_si[MAXN];
__device__ float g_sj[MAXN];
__device__ int   g_deg[MAXN];
__device__ int   g_start[MAXN];
__device__ int   g_cursor[MAXN];
__device__ int   g_sorted[MAXE];   // src ids grouped by dst (CSR adjacency)
__device__ int   g_bsum[SCAN_BLOCKS];
__device__ int   g_is64;

// ---------------------------------------------------------------------------
// Fused: edge-index dtype detection (block 0) + g_deg zeroing (all blocks).
// int64 little-endian values < 50000 have all-zero odd 32-bit words.
// ---------------------------------------------------------------------------
__global__ void detect_zero_kernel(const int* __restrict__ p, int twoE, int n) {
    int i = blockIdx.x * blockDim.x + threadIdx.x;
    if (i < n) g_deg[i] = 0;
    if (blockIdx.x == 0) {
        __shared__ int any_nonzero;
        if (threadIdx.x == 0) any_nonzero = 0;
        __syncthreads();
        int local = 0;
        int half = twoE >> 1;
        for (int k = threadIdx.x; k < 4096; k += blockDim.x) {
            long long q = (long long)k * half / 4096;
            long long idx = 2 * q + 1;
            if (idx < twoE) local |= p[idx];
        }
        if (local) atomicOr(&any_nonzero, 1);
        __syncthreads();
        if (threadIdx.x == 0) g_is64 = (any_nonzero == 0) ? 1 : 0;
    }
}

// ---------------------------------------------------------------------------
// CSR build: histogram -> 2-stage scan -> cursor scatter
// ---------------------------------------------------------------------------
__global__ void hist_kernel(const int* __restrict__ p, int E) {
    int e = blockIdx.x * blockDim.x + threadIdx.x;
    if (e >= E) return;
    int d = g_is64 ? p[2 * (E + e)] : p[E + e];
    atomicAdd(&g_deg[d], 1);
}

// Stage 1: per-block (1024-wide) exclusive scan; block total to g_bsum.
__global__ void scan_block_kernel(int n) {
    __shared__ int warp_tot[32];
    int tid = threadIdx.x;
    int lane = tid & 31;
    int wid = tid >> 5;
    int i = blockIdx.x * 1024 + tid;
    int v = (i < n) ? g_deg[i] : 0;
    int x = v;
#pragma unroll
    for (int o = 1; o < 32; o <<= 1) {
        int y = __shfl_up_sync(0xFFFFFFFFu, x, o);
        if (lane >= o) x += y;
    }
    if (lane == 31) warp_tot[wid] = x;
    __syncthreads();
    if (wid == 0) {
        int t = warp_tot[lane];
#pragma unroll
        for (int o = 1; o < 32; o <<= 1) {
            int y = __shfl_up_sync(0xFFFFFFFFu, t, o);
            if (lane >= o) t += y;
        }
        warp_tot[lane] = t;
    }
    __syncthreads();
    int off = wid ? warp_tot[wid - 1] : 0;
    int incl = x + off;
    if (i < n) g_start[i] = incl - v;
    if (tid == 1023) g_bsum[blockIdx.x] = incl;
}

// Stage 2 (fused): each 1024-block computes its own bsum prefix, then adds
// offsets and initializes cursors. nb <= 64.
__global__ void add_off_kernel(int n, int nb) {
    __shared__ int boff_s;
    int tid = threadIdx.x;
    int b = blockIdx.x;
    if (tid < 32) {
        // warp 0: prefix of bsum[0..b) via two-element-per-lane reduce
        int acc = 0;
#pragma unroll
        for (int j = 0; j < 2; j++) {
            int idx = tid + j * 32;
            if (idx < b && idx < nb) acc += g_bsum[idx];
        }
#pragma unroll
        for (int o = 16; o; o >>= 1)
            acc += __shfl_xor_sync(0xFFFFFFFFu, acc, o);
        if (tid == 0) boff_s = acc;
    }
    __syncthreads();
    int i = b * 1024 + tid;
    if (i < n) {
        int s = g_start[i] + boff_s;
        g_start[i] = s;
        g_cursor[i] = s;
    }
}

__global__ void scatter_kernel(const int* __restrict__ p, int E) {
    int e = blockIdx.x * blockDim.x + threadIdx.x;
    if (e >= E) return;
    int s, d;
    if (g_is64) { s = p[2 * e]; d = p[2 * (E + e)]; }
    else        { s = p[e];     d = p[E + e]; }
    int pos = atomicAdd(&g_cursor[d], 1);
    g_sorted[pos] = s;
}

// ---------------------------------------------------------------------------
// Encoder GEMM via tensor cores (fp16 in, fp32 accum):
// g_hh = fp16(relu(x[M,256] @ W[256,128] + b[128]))
// ---------------------------------------------------------------------------
__device__ __forceinline__ void ldsm_x4(unsigned* a, uint32_t addr) {
    asm volatile("ldmatrix.sync.aligned.m8n8.x4.shared.b16 {%0,%1,%2,%3}, [%4];"
                 : "=r"(a[0]), "=r"(a[1]), "=r"(a[2]), "=r"(a[3]) : "r"(addr));
}
__device__ __forceinline__ void ldsm_x2_trans(unsigned* b, uint32_t addr) {
    asm volatile("ldmatrix.sync.aligned.m8n8.x2.trans.shared.b16 {%0,%1}, [%2];"
                 : "=r"(b[0]), "=r"(b[1]) : "r"(addr));
}
__device__ __forceinline__ void mma16816(float* c, const unsigned* a, const unsigned* b) {
    asm volatile("mma.sync.aligned.m16n8k16.row.col.f32.f16.f16.f32 "
                 "{%0,%1,%2,%3}, {%4,%5,%6,%7}, {%8,%9}, {%0,%1,%2,%3};"
                 : "+f"(c[0]), "+f"(c[1]), "+f"(c[2]), "+f"(c[3])
                 : "r"(a[0]), "r"(a[1]), "r"(a[2]), "r"(a[3]),
                   "r"(b[0]), "r"(b[1]));
}

__global__ void __launch_bounds__(256) gemm_mma_kernel(
        const float* __restrict__ A, const float* __restrict__ W,
        const float* __restrict__ bias, int M) {
    const int LDA = 40;
    const int LDB = 136;
    __shared__ __half As[128 * LDA];
    __shared__ __half Bs[32 * LDB];

    int tid = threadIdx.x;
    int warp = tid >> 5;
    int lane = tid & 31;
    int warp_m = warp >> 2;
    int warp_n = warp & 3;
    int bm = blockIdx.x * 128;

    uint32_t sA = (uint32_t)__cvta_generic_to_shared(As);
    uint32_t sB = (uint32_t)__cvta_generic_to_shared(Bs);

    float c[4][4][4];
#pragma unroll
    for (int mt = 0; mt < 4; mt++)
#pragma unroll
        for (int nt = 0; nt < 4; nt++)
#pragma unroll
            for (int r = 0; r < 4; r++) c[mt][nt][r] = 0.f;

    for (int k0 = 0; k0 < 256; k0 += 32) {
#pragma unroll
        for (int i = 0; i < 4; i++) {
            int t = tid + i * 256;
            int r = t >> 3;
            int c4 = t & 7;
            int row = bm + r;
            float4 v = make_float4(0.f, 0.f, 0.f, 0.f);
            if (row < M)
                v = *(const float4*)(A + (size_t)row * 256 + k0 + c4 * 4);
            __half2 h01 = __floats2half2_rn(v.x, v.y);
            __half2 h23 = __floats2half2_rn(v.z, v.w);
            uint2 u = make_uint2(*(unsigned*)&h01, *(unsigned*)&h23);
            *(uint2*)(As + r * LDA + c4 * 4) = u;
        }
#pragma unroll
        for (int i = 0; i < 4; i++) {
            int t = tid + i * 256;
            int r = t >> 5;
            int c4 = t & 31;
            float4 v = *(const float4*)(W + (size_t)(k0 + r) * 128 + c4 * 4);
            __half2 h01 = __floats2half2_rn(v.x, v.y);
            __half2 h23 = __floats2half2_rn(v.z, v.w);
            uint2 u = make_uint2(*(unsigned*)&h01, *(unsigned*)&h23);
            *(uint2*)(Bs + r * LDB + c4 * 4) = u;
        }
        __syncthreads();
#pragma unroll
        for (int ks = 0; ks < 2; ks++) {
            int ko = ks * 16;
            unsigned a[4][4], b[4][2];
#pragma unroll
            for (int mt = 0; mt < 4; mt++) {
                uint32_t addr = sA + 2u * (uint32_t)((warp_m * 64 + mt * 16 + (lane & 15)) * LDA
                                           + ko + (lane >> 4) * 8);
                ldsm_x4(a[mt], addr);
            }
#pragma unroll
            for (int nt = 0; nt < 4; nt++) {
                uint32_t addr = sB + 2u * (uint32_t)((ko + (lane & 15)) * LDB
                                           + warp_n * 32 + nt * 8);
                ldsm_x2_trans(b[nt], addr);
            }
#pragma unroll
            for (int mt = 0; mt < 4; mt++)
#pragma unroll
                for (int nt = 0; nt < 4; nt++)
                    mma16816(c[mt][nt], a[mt], b[nt]);
        }
        __syncthreads();
    }

#pragma unroll
    for (int nt = 0; nt < 4; nt++) {
        int col = warp_n * 32 + nt * 8 + (lane & 3) * 2;
        float b0 = __ldg(bias + col);
        float b1 = __ldg(bias + col + 1);
#pragma unroll
        for (int mt = 0; mt < 4; mt++) {
            int row = bm + warp_m * 64 + mt * 16 + (lane >> 2);
            if (row < M) {
                float v0 = c[mt][nt][0] + b0;
                float v1 = c[mt][nt][1] + b1;
                __half2 h = __floats2half2_rn(v0 > 0.f ? v0 : 0.f,
                                              v1 > 0.f ? v1 : 0.f);
                *(__half2*)(g_hh + (size_t)row * HID + col) = h;
            }
            if (row + 8 < M) {
                float v0 = c[mt][nt][2] + b0;
                float v1 = c[mt][nt][3] + b1;
                __half2 h = __floats2half2_rn(v0 > 0.f ? v0 : 0.f,
                                              v1 > 0.f ? v1 : 0.f);
                *(__half2*)(g_hh + (size_t)(row + 8) * HID + col) = h;
            }
        }
    }
}

// ---------------------------------------------------------------------------
// Per-node attention scalars from fp16 features: si=h.w[:128], sj=h.w[128:]
// ---------------------------------------------------------------------------
__global__ void dots_kernel(const float* __restrict__ w, int n, int useB) {
    int warp = (blockIdx.x * blockDim.x + threadIdx.x) >> 5;
    int lane = threadIdx.x & 31;
    if (warp >= n) return;
    const __half* hp = (useB ? g_hbh : g_hh) + (size_t)warp * HID;
    uint2 raw = *((const uint2*)hp + lane);
    float2 f01 = __half22float2(*(__half2*)&raw.x);
    float2 f23 = __half22float2(*(__half2*)&raw.y);
    float4 wi = ((const float4*)w)[lane];
    float4 wj = ((const float4*)w)[32 + lane];
    float si = f01.x * wi.x + f01.y * wi.y + f23.x * wi.z + f23.y * wi.w;
    float sj = f01.x * wj.x + f01.y * wj.y + f23.x * wj.z + f23.y * wj.w;
#pragma unroll
    for (int o = 16; o; o >>= 1) {
        si += __shfl_xor_sync(0xFFFFFFFFu, si, o);
        sj += __shfl_xor_sync(0xFFFFFFFFu, sj, o);
    }
    if (lane == 0) { g_si[warp] = si; g_sj[warp] = sj; }
}

// ---------------------------------------------------------------------------
// Aggregation, 2 edges per warp step: 16 lanes per edge, uint4 (8-half) loads.
// Lane L (half h = L>>4, sub = L&15) accumulates features [sub*8, sub*8+8)
// over edges k0+h, k0+h+2, ... Final shfl_xor(16) combines the two halves.
// ---------------------------------------------------------------------------
__device__ __forceinline__ void agg_accum(const __half* __restrict__ feat,
                                          int k0, int deg, float si, float b,
                                          int half, int sub, float* acc) {
#pragma unroll
    for (int r = 0; r < 8; r++) acc[r] = 0.f;
    int kend = k0 + deg;
#pragma unroll 4
    for (int k = k0 + half; k < kend; k += 2) {
        int s = g_sorted[k];
        float z = si + g_sj[s] + b;
        float alpha = 1.0f / (1.0f + __expf(-z));
        uint4 raw = *((const uint4*)(feat + (size_t)s * HID) + sub);
        float2 f0 = __half22float2(*(__half2*)&raw.x);
        float2 f1 = __half22float2(*(__half2*)&raw.y);
        float2 f2 = __half22float2(*(__half2*)&raw.z);
        float2 f3 = __half22float2(*(__half2*)&raw.w);
        acc[0] += alpha * f0.x; acc[1] += alpha * f0.y;
        acc[2] += alpha * f1.x; acc[3] += alpha * f1.y;
        acc[4] += alpha * f2.x; acc[5] += alpha * f2.y;
        acc[6] += alpha * f3.x; acc[7] += alpha * f3.y;
    }
#pragma unroll
    for (int r = 0; r < 8; r++)
        acc[r] += __shfl_xor_sync(0xFFFFFFFFu, acc[r], 16);
}

// Layer 1: g_hbh[d] = fp16(relu(acc / max(deg,1)))
__global__ void agg1_kernel(const float* __restrict__ bptr, int n) {
    int d = (blockIdx.x * blockDim.x + threadIdx.x) >> 5;
    int lane = threadIdx.x & 31;
    if (d >= n) return;
    int half = lane >> 4, sub = lane & 15;
    float acc[8];
    agg_accum(g_hh, g_start[d], g_deg[d], g_si[d], bptr[0], half, sub, acc);
    int deg = g_deg[d];
    float inv = 1.0f / (float)(deg < 1 ? 1 : deg);
    if (half == 0) {
        __half2 h01 = __floats2half2_rn(fmaxf(acc[0] * inv, 0.f), fmaxf(acc[1] * inv, 0.f));
        __half2 h23 = __floats2half2_rn(fmaxf(acc[2] * inv, 0.f), fmaxf(acc[3] * inv, 0.f));
        __half2 h45 = __floats2half2_rn(fmaxf(acc[4] * inv, 0.f), fmaxf(acc[5] * inv, 0.f));
        __half2 h67 = __floats2half2_rn(fmaxf(acc[6] * inv, 0.f), fmaxf(acc[7] * inv, 0.f));
        uint4 u;
        u.x = *(unsigned*)&h01; u.y = *(unsigned*)&h23;
        u.z = *(unsigned*)&h45; u.w = *(unsigned*)&h67;
        *((uint4*)(g_hbh + (size_t)d * HID) + sub) = u;
    }
}

// Layer 2 + classifier: out[d] = (acc/max(deg,1)) @ cls_w + cls_b
__global__ void agg2_cls_kernel(const float* __restrict__ bptr,
                                const float* __restrict__ clsw,
                                const float* __restrict__ clsb,
                                float* __restrict__ out, int n) {
    int d = (blockIdx.x * blockDim.x + threadIdx.x) >> 5;
    int lane = threadIdx.x & 31;
    if (d >= n) return;
    int half = lane >> 4, sub = lane & 15;
    float acc[8];
    agg_accum(g_hbh, g_start[d], g_deg[d], g_si[d], bptr[0], half, sub, acc);
    int deg = g_deg[d];
    float inv = 1.0f / (float)(deg < 1 ? 1 : deg);
    // all 32 lanes hold identical combined sums for features [sub*8, sub*8+8)
    float o0 = 0.f, o1 = 0.f;
#pragma unroll
    for (int r = 0; r < 8; r++) {
        float v = acc[r] * inv;
        int j = sub * 8 + r;
        o0 += v * clsw[j * 2];
        o1 += v * clsw[j * 2 + 1];
    }
    // reduce over the 16 subs (lanes 0-15 and 16-31 are duplicates)
#pragma unroll
    for (int o = 8; o; o >>= 1) {
        o0 += __shfl_xor_sync(0xFFFFFFFFu, o0, o);
        o1 += __shfl_xor_sync(0xFFFFFFFFu, o1, o);
    }
    if (lane == 0) {
        out[(size_t)d * 2 + 0] = o0 + clsb[0];
        out[(size_t)d * 2 + 1] = o1 + clsb[1];
    }
}

// ---------------------------------------------------------------------------
extern "C" void kernel_launch(void* const* d_in, const int* in_sizes, int n_in,
                              void* d_out, int out_size) {
    const float* x      = (const float*)d_in[0];
    const int*   ei     = (const int*)  d_in[1];
    const float* enc_w  = (const float*)d_in[2];
    const float* enc_b  = (const float*)d_in[3];
    const float* att1_w = (const float*)d_in[4];
    const float* att1_b = (const float*)d_in[5];
    const float* att2_w = (const float*)d_in[6];
    const float* att2_b = (const float*)d_in[7];
    const float* cls_w  = (const float*)d_in[8];
    const float* cls_b  = (const float*)d_in[9];
    float* out = (float*)d_out;

    int N = in_sizes[0] / 256;
    int E = in_sizes[1] / 2;
    int nb = (N + 1023) / 1024;

    // Decode dtype + zero degrees; CSR build (grouped by dst).
    detect_zero_kernel<<<(N + 1023) / 1024, 1024>>>(ei, 2 * E, N);
    hist_kernel<<<(E + 255) / 256, 256>>>(ei, E);
    scan_block_kernel<<<nb, 1024>>>(N);
    add_off_kernel<<<nb, 1024>>>(N, nb);
    scatter_kernel<<<(E + 255) / 256, 256>>>(ei, E);

    // Encoder (tensor cores)
    gemm_mma_kernel<<<(N + 127) / 128, 256>>>(x, enc_w, enc_b, N);

    int node_warp_blocks = (N + 7) / 8;  // warp per node, 8 warps/block

    // Layer 1
    dots_kernel<<<node_warp_blocks, 256>>>(att1_w, N, 0);
    agg1_kernel<<<node_warp_blocks, 256>>>(att1_b, N);

    // Layer 2 (+ classifier)
    dots_kernel<<<node_warp_blocks, 256>>>(att2_w, N, 1);
    agg2_cls_kernel<<<node_warp_blocks, 256>>>(att2_b, cls_w, cls_b, out, N);
}

// round 7
// speedup vs baseline: 1.9541x; 1.1311x over previous
#include <cuda_runtime.h>
#include <cuda_fp16.h>
#include <cstdint>

#define HID 128
#define MAXN 50176
#define MAXE 1605632
#define SCAN_BLOCKS 64

__device__ __align__(16) __half g_hh [(size_t)MAXN * HID];  // layer-0 features (fp16)
__device__ __align__(16) __half g_hbh[(size_t)MAXN * HID];  // layer-1 features (fp16)
__device__ float g_si [MAXN];   // layer-1 attention scalars
__device__ float g_sj [MAXN];
__device__ float g_si2[MAXN];   // layer-2 attention scalars
__device__ float g_sj2[MAXN];
__device__ int   g_deg[MAXN];   // INVARIANT: all-zero at kernel_launch entry
__device__ int   g_start[MAXN];
__device__ int   g_cursor[MAXN];
__device__ int   g_sorted[MAXE];
__device__ int   g_bsum[SCAN_BLOCKS];

// ---------------------------------------------------------------------------
// Inline edge-dtype detection (per warp, no global state):
// samples odd int32 words 1,3,...,255. int64 (values<50000) -> all zero.
// ---------------------------------------------------------------------------
__device__ __forceinline__ int detect_is64(const int* __restrict__ p) {
    int lane = threadIdx.x & 31;
    unsigned v = 0;
#pragma unroll
    for (int j = 0; j < 4; j++)
        v |= (unsigned)p[2 * (lane * 4 + j) + 1];
    unsigned any = __ballot_sync(0xFFFFFFFFu, v != 0);
    return any == 0;
}

// ---------------------------------------------------------------------------
// GEMM helpers (fp16 mma, fp32 accum)
// ---------------------------------------------------------------------------
__device__ __forceinline__ void ldsm_x4(unsigned* a, uint32_t addr) {
    asm volatile("ldmatrix.sync.aligned.m8n8.x4.shared.b16 {%0,%1,%2,%3}, [%4];"
                 : "=r"(a[0]), "=r"(a[1]), "=r"(a[2]), "=r"(a[3]) : "r"(addr));
}
__device__ __forceinline__ void ldsm_x2_trans(unsigned* b, uint32_t addr) {
    asm volatile("ldmatrix.sync.aligned.m8n8.x2.trans.shared.b16 {%0,%1}, [%2];"
                 : "=r"(b[0]), "=r"(b[1]) : "r"(addr));
}
__device__ __forceinline__ void mma16816(float* c, const unsigned* a, const unsigned* b) {
    asm volatile("mma.sync.aligned.m16n8k16.row.col.f32.f16.f16.f32 "
                 "{%0,%1,%2,%3}, {%4,%5,%6,%7}, {%8,%9}, {%0,%1,%2,%3};"
                 : "+f"(c[0]), "+f"(c[1]), "+f"(c[2]), "+f"(c[3])
                 : "r"(a[0]), "r"(a[1]), "r"(a[2]), "r"(a[3]),
                   "r"(b[0]), "r"(b[1]));
}

// ---------------------------------------------------------------------------
// Mega-kernel A: blocks [0,Ggemm) do encoder GEMM tiles; the rest do the
// dst-degree histogram (edge decode inline).
// ---------------------------------------------------------------------------
__global__ void __launch_bounds__(256) gemm_hist_kernel(
        const float* __restrict__ A, const float* __restrict__ W,
        const float* __restrict__ bias, const int* __restrict__ ei,
        int M, int E, int Ggemm) {
    const int LDA = 40;
    const int LDB = 136;
    __shared__ __half As[128 * LDA];
    __shared__ __half Bs[32 * LDB];

    if (blockIdx.x >= Ggemm) {
        // ---- histogram path ----
        int is64 = detect_is64(ei);
        int base = (blockIdx.x - Ggemm) * 2048 + threadIdx.x;
#pragma unroll
        for (int i = 0; i < 8; i++) {
            int e = base + i * 256;
            if (e < E) {
                int d = is64 ? ei[2 * (E + e)] : ei[E + e];
                atomicAdd(&g_deg[d], 1);
            }
        }
        return;
    }

    // ---- GEMM path ----
    int tid = threadIdx.x;
    int warp = tid >> 5;
    int lane = tid & 31;
    int warp_m = warp >> 2;
    int warp_n = warp & 3;
    int bm = blockIdx.x * 128;

    uint32_t sA = (uint32_t)__cvta_generic_to_shared(As);
    uint32_t sB = (uint32_t)__cvta_generic_to_shared(Bs);

    float c[4][4][4];
#pragma unroll
    for (int mt = 0; mt < 4; mt++)
#pragma unroll
        for (int nt = 0; nt < 4; nt++)
#pragma unroll
            for (int r = 0; r < 4; r++) c[mt][nt][r] = 0.f;

    for (int k0 = 0; k0 < 256; k0 += 32) {
#pragma unroll
        for (int i = 0; i < 4; i++) {
            int t = tid + i * 256;
            int r = t >> 3;
            int c4 = t & 7;
            int row = bm + r;
            float4 v = make_float4(0.f, 0.f, 0.f, 0.f);
            if (row < M)
                v = *(const float4*)(A + (size_t)row * 256 + k0 + c4 * 4);
            __half2 h01 = __floats2half2_rn(v.x, v.y);
            __half2 h23 = __floats2half2_rn(v.z, v.w);
            uint2 u = make_uint2(*(unsigned*)&h01, *(unsigned*)&h23);
            *(uint2*)(As + r * LDA + c4 * 4) = u;
        }
#pragma unroll
        for (int i = 0; i < 4; i++) {
            int t = tid + i * 256;
            int r = t >> 5;
            int c4 = t & 31;
            float4 v = *(const float4*)(W + (size_t)(k0 + r) * 128 + c4 * 4);
            __half2 h01 = __floats2half2_rn(v.x, v.y);
            __half2 h23 = __floats2half2_rn(v.z, v.w);
            uint2 u = make_uint2(*(unsigned*)&h01, *(unsigned*)&h23);
            *(uint2*)(Bs + r * LDB + c4 * 4) = u;
        }
        __syncthreads();
#pragma unroll
        for (int ks = 0; ks < 2; ks++) {
            int ko = ks * 16;
            unsigned a[4][4], b[4][2];
#pragma unroll
            for (int mt = 0; mt < 4; mt++) {
                uint32_t addr = sA + 2u * (uint32_t)((warp_m * 64 + mt * 16 + (lane & 15)) * LDA
                                           + ko + (lane >> 4) * 8);
                ldsm_x4(a[mt], addr);
            }
#pragma unroll
            for (int nt = 0; nt < 4; nt++) {
                uint32_t addr = sB + 2u * (uint32_t)((ko + (lane & 15)) * LDB
                                           + warp_n * 32 + nt * 8);
                ldsm_x2_trans(b[nt], addr);
            }
#pragma unroll
            for (int mt = 0; mt < 4; mt++)
#pragma unroll
                for (int nt = 0; nt < 4; nt++)
                    mma16816(c[mt][nt], a[mt], b[nt]);
        }
        __syncthreads();
    }

#pragma unroll
    for (int nt = 0; nt < 4; nt++) {
        int col = warp_n * 32 + nt * 8 + (lane & 3) * 2;
        float b0 = __ldg(bias + col);
        float b1 = __ldg(bias + col + 1);
#pragma unroll
        for (int mt = 0; mt < 4; mt++) {
            int row = bm + warp_m * 64 + mt * 16 + (lane >> 2);
            if (row < M) {
                float v0 = c[mt][nt][0] + b0;
                float v1 = c[mt][nt][1] + b1;
                __half2 h = __floats2half2_rn(v0 > 0.f ? v0 : 0.f,
                                              v1 > 0.f ? v1 : 0.f);
                *(__half2*)(g_hh + (size_t)row * HID + col) = h;
            }
            if (row + 8 < M) {
                float v0 = c[mt][nt][2] + b0;
                float v1 = c[mt][nt][3] + b1;
                __half2 h = __floats2half2_rn(v0 > 0.f ? v0 : 0.f,
                                              v1 > 0.f ? v1 : 0.f);
                *(__half2*)(g_hh + (size_t)(row + 8) * HID + col) = h;
            }
        }
    }
}

// ---------------------------------------------------------------------------
// CSR scan stages (unchanged)
// ---------------------------------------------------------------------------
__global__ void scan_block_kernel(int n) {
    __shared__ int warp_tot[32];
    int tid = threadIdx.x;
    int lane = tid & 31;
    int wid = tid >> 5;
    int i = blockIdx.x * 1024 + tid;
    int v = (i < n) ? g_deg[i] : 0;
    int x = v;
#pragma unroll
    for (int o = 1; o < 32; o <<= 1) {
        int y = __shfl_up_sync(0xFFFFFFFFu, x, o);
        if (lane >= o) x += y;
    }
    if (lane == 31) warp_tot[wid] = x;
    __syncthreads();
    if (wid == 0) {
        int t = warp_tot[lane];
#pragma unroll
        for (int o = 1; o < 32; o <<= 1) {
            int y = __shfl_up_sync(0xFFFFFFFFu, t, o);
            if (lane >= o) t += y;
        }
        warp_tot[lane] = t;
    }
    __syncthreads();
    int off = wid ? warp_tot[wid - 1] : 0;
    int incl = x + off;
    if (i < n) g_start[i] = incl - v;
    if (tid == 1023) g_bsum[blockIdx.x] = incl;
}

__global__ void add_off_kernel(int n, int nb) {
    __shared__ int boff_s;
    int tid = threadIdx.x;
    int b = blockIdx.x;
    if (tid < 32) {
        int acc = 0;
#pragma unroll
        for (int j = 0; j < 2; j++) {
            int idx = tid + j * 32;
            if (idx < b && idx < nb) acc += g_bsum[idx];
        }
#pragma unroll
        for (int o = 16; o; o >>= 1)
            acc += __shfl_xor_sync(0xFFFFFFFFu, acc, o);
        if (tid == 0) boff_s = acc;
    }
    __syncthreads();
    int i = b * 1024 + tid;
    if (i < n) {
        int s = g_start[i] + boff_s;
        g_start[i] = s;
        g_cursor[i] = s;
    }
}

// ---------------------------------------------------------------------------
// Mega-kernel B: blocks [0,Gs) do CSR scatter; the rest do layer-1 dots
// (si = h.w[:128], sj = h.w[128:], one warp per node).
// ---------------------------------------------------------------------------
__global__ void __launch_bounds__(256) scatter_dots_kernel(
        const int* __restrict__ ei, const float* __restrict__ w,
        int E, int n, int Gs) {
    if (blockIdx.x < Gs) {
        int is64 = detect_is64(ei);
        int base = blockIdx.x * 2048 + threadIdx.x;
#pragma unroll
        for (int i = 0; i < 8; i++) {
            int e = base + i * 256;
            if (e < E) {
                int s, d;
                if (is64) { s = ei[2 * e]; d = ei[2 * (E + e)]; }
                else      { s = ei[e];     d = ei[E + e]; }
                int pos = atomicAdd(&g_cursor[d], 1);
                g_sorted[pos] = s;
            }
        }
        return;
    }
    int node = (blockIdx.x - Gs) * 8 + (threadIdx.x >> 5);
    int lane = threadIdx.x & 31;
    if (node >= n) return;
    uint2 raw = *((const uint2*)(g_hh + (size_t)node * HID) + lane);
    float2 f01 = __half22float2(*(__half2*)&raw.x);
    float2 f23 = __half22float2(*(__half2*)&raw.y);
    float4 wi = ((const float4*)w)[lane];
    float4 wj = ((const float4*)w)[32 + lane];
    float si = f01.x * wi.x + f01.y * wi.y + f23.x * wi.z + f23.y * wi.w;
    float sj = f01.x * wj.x + f01.y * wj.y + f23.x * wj.z + f23.y * wj.w;
#pragma unroll
    for (int o = 16; o; o >>= 1) {
        si += __shfl_xor_sync(0xFFFFFFFFu, si, o);
        sj += __shfl_xor_sync(0xFFFFFFFFu, sj, o);
    }
    if (lane == 0) { g_si[node] = si; g_sj[node] = sj; }
}

// ---------------------------------------------------------------------------
// Shared gather-accumulate: 2 edges per warp step, 16 lanes/edge, uint4 loads.
// After the xor(16) combine ALL lanes hold the full sums for features
// [sub*8, sub*8+8), sub = lane&15.
// ---------------------------------------------------------------------------
__device__ __forceinline__ void agg_accum(const __half* __restrict__ feat,
                                          const float* __restrict__ sj_tab,
                                          int k0, int deg, float sib,
                                          int half, int sub, float* acc) {
#pragma unroll
    for (int r = 0; r < 8; r++) acc[r] = 0.f;
    int kend = k0 + deg;
#pragma unroll 4
    for (int k = k0 + half; k < kend; k += 2) {
        int s = g_sorted[k];
        float z = sib + sj_tab[s];
        float alpha = 1.0f / (1.0f + __expf(-z));
        uint4 raw = *((const uint4*)(feat + (size_t)s * HID) + sub);
        float2 f0 = __half22float2(*(__half2*)&raw.x);
        float2 f1 = __half22float2(*(__half2*)&raw.y);
        float2 f2 = __half22float2(*(__half2*)&raw.z);
        float2 f3 = __half22float2(*(__half2*)&raw.w);
        acc[0] += alpha * f0.x; acc[1] += alpha * f0.y;
        acc[2] += alpha * f1.x; acc[3] += alpha * f1.y;
        acc[4] += alpha * f2.x; acc[5] += alpha * f2.y;
        acc[6] += alpha * f3.x; acc[7] += alpha * f3.y;
    }
#pragma unroll
    for (int r = 0; r < 8; r++)
        acc[r] += __shfl_xor_sync(0xFFFFFFFFu, acc[r], 16);
}

// ---------------------------------------------------------------------------
// Layer 1 + fused layer-2 dots:
// g_hbh[d] = fp16(relu(acc/max(deg,1))); g_si2/g_sj2[d] = hb . att2_w halves.
// ---------------------------------------------------------------------------
__global__ void agg1_kernel(const float* __restrict__ bptr,
                            const float* __restrict__ att2w, int n) {
    int d = (blockIdx.x * blockDim.x + threadIdx.x) >> 5;
    int lane = threadIdx.x & 31;
    if (d >= n) return;
    int half = lane >> 4, sub = lane & 15;
    float acc[8];
    float sib = g_si[d] + bptr[0];
    agg_accum(g_hh, g_sj, g_start[d], g_deg[d], sib, half, sub, acc);
    int deg = g_deg[d];
    float inv = 1.0f / (float)(deg < 1 ? 1 : deg);
    __half2 h01 = __floats2half2_rn(fmaxf(acc[0] * inv, 0.f), fmaxf(acc[1] * inv, 0.f));
    __half2 h23 = __floats2half2_rn(fmaxf(acc[2] * inv, 0.f), fmaxf(acc[3] * inv, 0.f));
    __half2 h45 = __floats2half2_rn(fmaxf(acc[4] * inv, 0.f), fmaxf(acc[5] * inv, 0.f));
    __half2 h67 = __floats2half2_rn(fmaxf(acc[6] * inv, 0.f), fmaxf(acc[7] * inv, 0.f));
    if (half == 0) {
        uint4 u;
        u.x = *(unsigned*)&h01; u.y = *(unsigned*)&h23;
        u.z = *(unsigned*)&h45; u.w = *(unsigned*)&h67;
        *((uint4*)(g_hbh + (size_t)d * HID) + sub) = u;
    }
    // fused layer-2 dots from the fp16-rounded values
    float f[8];
    float2 t;
    t = __half22float2(h01); f[0] = t.x; f[1] = t.y;
    t = __half22float2(h23); f[2] = t.x; f[3] = t.y;
    t = __half22float2(h45); f[4] = t.x; f[5] = t.y;
    t = __half22float2(h67); f[6] = t.x; f[7] = t.y;
    int j = sub * 8;
    float4 wi0 = *(const float4*)(att2w + j);
    float4 wi1 = *(const float4*)(att2w + j + 4);
    float4 wj0 = *(const float4*)(att2w + 128 + j);
    float4 wj1 = *(const float4*)(att2w + 128 + j + 4);
    float si = f[0]*wi0.x + f[1]*wi0.y + f[2]*wi0.z + f[3]*wi0.w
             + f[4]*wi1.x + f[5]*wi1.y + f[6]*wi1.z + f[7]*wi1.w;
    float sj = f[0]*wj0.x + f[1]*wj0.y + f[2]*wj0.z + f[3]*wj0.w
             + f[4]*wj1.x + f[5]*wj1.y + f[6]*wj1.z + f[7]*wj1.w;
    if (half) { si = 0.f; sj = 0.f; }
#pragma unroll
    for (int o = 16; o; o >>= 1) {
        si += __shfl_xor_sync(0xFFFFFFFFu, si, o);
        sj += __shfl_xor_sync(0xFFFFFFFFu, sj, o);
    }
    if (lane == 0) { g_si2[d] = si; g_sj2[d] = sj; }
}

// ---------------------------------------------------------------------------
// Layer 2 + classifier; restores g_deg invariant (zeroes it after last use).
// ---------------------------------------------------------------------------
__global__ void agg2_cls_kernel(const float* __restrict__ bptr,
                                const float* __restrict__ clsw,
                                const float* __restrict__ clsb,
                                float* __restrict__ out, int n) {
    int d = (blockIdx.x * blockDim.x + threadIdx.x) >> 5;
    int lane = threadIdx.x & 31;
    if (d >= n) return;
    int half = lane >> 4, sub = lane & 15;
    float acc[8];
    float sib = g_si2[d] + bptr[0];
    agg_accum(g_hbh, g_sj2, g_start[d], g_deg[d], sib, half, sub, acc);
    int deg = g_deg[d];
    if (lane == 0) g_deg[d] = 0;   // restore invariant for next replay
    float inv = 1.0f / (float)(deg < 1 ? 1 : deg);
    float o0 = 0.f, o1 = 0.f;
#pragma unroll
    for (int r = 0; r < 8; r++) {
        float v = acc[r] * inv;
        int j = sub * 8 + r;
        o0 += v * clsw[j * 2];
        o1 += v * clsw[j * 2 + 1];
    }
#pragma unroll
    for (int o = 8; o; o >>= 1) {
        o0 += __shfl_xor_sync(0xFFFFFFFFu, o0, o);
        o1 += __shfl_xor_sync(0xFFFFFFFFu, o1, o);
    }
    if (lane == 0) {
        out[(size_t)d * 2 + 0] = o0 + clsb[0];
        out[(size_t)d * 2 + 1] = o1 + clsb[1];
    }
}

// ---------------------------------------------------------------------------
extern "C" void kernel_launch(void* const* d_in, const int* in_sizes, int n_in,
                              void* d_out, int out_size) {
    const float* x      = (const float*)d_in[0];
    const int*   ei     = (const int*)  d_in[1];
    const float* enc_w  = (const float*)d_in[2];
    const float* enc_b  = (const float*)d_in[3];
    const float* att1_w = (const float*)d_in[4];
    const float* att1_b = (const float*)d_in[5];
    const float* att2_w = (const float*)d_in[6];
    const float* att2_b = (const float*)d_in[7];
    const float* cls_w  = (const float*)d_in[8];
    const float* cls_b  = (const float*)d_in[9];
    float* out = (float*)d_out;

    int N = in_sizes[0] / 256;
    int E = in_sizes[1] / 2;
    int nb = (N + 1023) / 1024;
    int Ggemm = (N + 127) / 128;
    int Gh = (E + 2047) / 2048;
    int Gd = (N + 7) / 8;

    // A: encoder GEMM (tensor cores) overlapped with dst histogram
    gemm_hist_kernel<<<Ggemm + Gh, 256>>>(x, enc_w, enc_b, ei, N, E, Ggemm);
    // CSR offsets
    scan_block_kernel<<<nb, 1024>>>(N);
    add_off_kernel<<<nb, 1024>>>(N, nb);
    // B: CSR scatter overlapped with layer-1 attention dots
    scatter_dots_kernel<<<Gh + Gd, 256>>>(ei, att1_w, E, N, Gh);
    // Layer 1 (+ fused layer-2 dots)
    agg1_kernel<<<Gd, 256>>>(att1_b, att2_w, N);
    // Layer 2 + classifier (+ deg invariant restore)
    agg2_cls_kernel<<<Gd, 256>>>(att2_b, cls_w, cls_b, out, N);
}